// round 16
// baseline (speedup 1.0000x reference)
#include <cuda_runtime.h>
#include <math.h>

#define TSTEPS 512
#define BATCH  64
#define DIN    256
#define HID    512
#define DOUT   256
#define G4H    2048
#define NBLK   128
#define NCH    4      // batch chains
#define BCH    16     // batches per chain
#define LA     4      // proj lookahead (steps)
#define NRING  6      // smem G ring slots (> LA+1)

typedef unsigned long long ull;

// ---------------- scratch ----------------
__device__ float d_hq[NCH][2][256 * BCH * 2];             // [chain][parity][kpair][b16][2]
__device__ float d_cbuf[HID * BATCH];                     // [u][b]
__device__ float d_hs[(size_t)TSTEPS * HID * BATCH];      // [t][u][b]
__device__ float d_logits[(size_t)TSTEPS * BATCH * DOUT]; // [t][b][n]
__device__ unsigned d_cntg[NCH * 8 * 32];                 // group counters (stride-32 lines)
__device__ unsigned d_cntr[NCH * 32];                     // root counters
__device__ volatile int d_epoch[NCH * 32];                // broadcast line per chain

// ---------------- helpers ----------------
__device__ __forceinline__ void fma2(ull& a, ull x, ull y) {
    asm("fma.rn.f32x2 %0, %1, %2, %3;" : "=l"(a) : "l"(x), "l"(y), "l"(a));
}
__device__ __forceinline__ void fadd2(ull& a, ull x) {
    asm("add.rn.f32x2 %0, %1, %2;" : "=l"(a) : "l"(a), "l"(x));
}
__device__ __forceinline__ ull pack2(float lo, float hi) {
    ull r; asm("mov.b64 %0, {%1, %2};" : "=l"(r) : "f"(lo), "f"(hi)); return r;
}
__device__ __forceinline__ float sum2(ull v) {
    float lo, hi; asm("mov.b64 {%0, %1}, %2;" : "=f"(lo), "=f"(hi) : "l"(v));
    return lo + hi;
}
__device__ __forceinline__ ull ldcg64(const ull* p) {
    ull v; asm volatile("ld.global.cg.u64 %0, [%1];" : "=l"(v) : "l"(p)); return v;
}
__device__ __forceinline__ int ld_acq(const volatile int* p) {
    int v; asm volatile("ld.acquire.gpu.global.s32 %0, [%1];" : "=r"(v) : "l"(p) : "memory");
    return v;
}
__device__ __forceinline__ void st_rel(volatile int* p, int v) {
    asm volatile("st.release.gpu.global.s32 [%0], %1;" :: "l"(p), "r"(v) : "memory");
}
__device__ __forceinline__ void barx(int id) {
    asm volatile("bar.sync %0, 128;" :: "r"(id) : "memory");
}
__device__ __forceinline__ float fsig(float x) {
    return __fdividef(1.0f, 1.0f + __expf(-x));
}
__device__ __forceinline__ float ftanh(float x) {
    float e = __expf(2.0f * x);                 // inf-safe
    return 1.0f - __fdividef(2.0f, e + 1.0f);
}

// ---------------- init: pack initial h/c per chain, reset sync state ----------------
__global__ __launch_bounds__(256) void init_state(const float* __restrict__ h0,
                                                  const float* __restrict__ c0) {
    int i = blockIdx.x * blockDim.x + threadIdx.x;
    if (i < NCH * 8) d_cntg[i * 32] = 0u;
    if (i < NCH) { d_cntr[i * 32] = 0u; d_epoch[i * 32] = 0; }
    if (i >= HID * BATCH) return;
    int b = i >> 9;                 // h0 layout [1][B][H]
    int u = i & 511;
    int q = b >> 4, b16 = b & 15;
    d_hq[q][0][((u >> 1) * BCH + b16) * 2 + (u & 1)] = h0[i];
    d_cbuf[u * BATCH + b] = c0[i];
}

// ---------------- register-blocked GEMM (used for FC only now) ----------------
__global__ __launch_bounds__(256, 2) void gemm_kernel(
    const float* __restrict__ X, const float* __restrict__ W,
    const float* __restrict__ bias, float* __restrict__ Out,
    int Ntot, int K, int kchunks) {
    __shared__ ull Wt[16 * 130];
    __shared__ ull Xt[16 * 66];

    int t  = blockIdx.y;
    int n0 = blockIdx.x * 128;
    int tid = threadIdx.x;
    int tx = tid & 15, ty = tid >> 4;

    ull acc[8][4];
#pragma unroll
    for (int i = 0; i < 8; i++)
#pragma unroll
        for (int j = 0; j < 4; j++) acc[i][j] = 0ull;

    for (int ch = 0; ch < kchunks; ch++) {
        for (int idx = tid; idx < 2048; idx += 256) {
            int kk = idx & 15, n = idx >> 4;
            Wt[kk * 130 + n] = *(const ull*)(W + (size_t)(n0 + n) * K + ch * 32 + kk * 2);
        }
        for (int idx = tid; idx < 1024; idx += 256) {
            int b = idx & 63, kk = idx >> 6;
            int kg = ch * 32 + kk * 2;
            Xt[kk * 66 + b] = pack2(X[((size_t)t * K + kg) * 64 + b],
                                    X[((size_t)t * K + kg + 1) * 64 + b]);
        }
        __syncthreads();
#pragma unroll
        for (int kk = 0; kk < 16; kk++) {
            ulonglong2 xv0 = *(const ulonglong2*)&Xt[kk * 66 + tx * 4];
            ulonglong2 xv1 = *(const ulonglong2*)&Xt[kk * 66 + tx * 4 + 2];
            ull xs0 = xv0.x, xs1 = xv0.y, xs2 = xv1.x, xs3 = xv1.y;
#pragma unroll
            for (int q = 0; q < 4; q++) {
                ulonglong2 wv = *(const ulonglong2*)&Wt[kk * 130 + ty * 8 + 2 * q];
                fma2(acc[2 * q][0], wv.x, xs0);
                fma2(acc[2 * q][1], wv.x, xs1);
                fma2(acc[2 * q][2], wv.x, xs2);
                fma2(acc[2 * q][3], wv.x, xs3);
                fma2(acc[2 * q + 1][0], wv.y, xs0);
                fma2(acc[2 * q + 1][1], wv.y, xs1);
                fma2(acc[2 * q + 1][2], wv.y, xs2);
                fma2(acc[2 * q + 1][3], wv.y, xs3);
            }
        }
        __syncthreads();
    }

    // Out[t][b][n]
    float bb[8];
#pragma unroll
    for (int i = 0; i < 8; i++) bb[i] = bias[n0 + ty * 8 + i];
#pragma unroll
    for (int j = 0; j < 4; j++) {
        int b = tx * 4 + j;
        float v[8];
#pragma unroll
        for (int i = 0; i < 8; i++) v[i] = sum2(acc[i][j]) + bb[i];
        float* op = Out + ((size_t)t * 64 + b) * Ntot + n0 + ty * 8;
        *(float4*)op       = make_float4(v[0], v[1], v[2], v[3]);
        *(float4*)(op + 4) = make_float4(v[4], v[5], v[6], v[7]);
    }
}

// ---------------- fused proj P-phase ----------------
// Thread (q, wi, kh, b16): rows r in [kh*8, kh*8+8), kpairs [wi*32, wi*32+32),
// batch q*16+b16, for proj target step tp. Writes 8 partials to red2.
// X layout [T][B][256]; row used = tp - shift (shift=1 for decoder); tp==0 && shift -> zeros.
__device__ __forceinline__ void proj_phase(const ull* __restrict__ wih,
                                           ull* __restrict__ red2q,
                                           const float* __restrict__ X,
                                           int tp, int shift,
                                           int q, int wi, int kh, int b16) {
    ull acc2[8];
#pragma unroll
    for (int j = 0; j < 8; j++) acc2[j] = 0ull;
    if (!(shift && tp == 0)) {
        const ull* xr = (const ull*)(X + ((size_t)(tp - shift) * 64 + q * 16 + b16) * 256
                                       + wi * 64);
#pragma unroll
        for (int ch = 0; ch < 4; ch++) {
            ull xv[8];
#pragma unroll
            for (int i = 0; i < 8; i++) xv[i] = xr[ch * 8 + i];
#pragma unroll
            for (int i = 0; i < 8; i++) {
                const ulonglong2* wp =
                    (const ulonglong2*)(wih + (size_t)(wi * 32 + ch * 8 + i) * 16 + kh * 8);
#pragma unroll
                for (int jp = 0; jp < 4; jp++) {
                    ulonglong2 wv = wp[jp];
                    fma2(acc2[2 * jp],     wv.x, xv[i]);
                    fma2(acc2[2 * jp + 1], wv.y, xv[i]);
                }
            }
        }
    }
#pragma unroll
    for (int j = 0; j < 8; j++) {
        int r = kh * 8 + j;
        red2q[(size_t)(r * 16 + b16) * 5 + wi] = acc2[j];
    }
}

// ---------------- persistent recurrent LSTM with fused input projection ----------------
// R14 recurrence (4 chains, tree-atomic arrival) + in-loop proj of G[t+LA] into a
// smem ring. The proj FMA runs BEFORE the epoch wait each step, filling the idle
// issue slots the sync otherwise wastes. Bias is added in the epilogue.
__global__ __launch_bounds__(512) void recur_kernel(const float* __restrict__ Whh,
                                                    int which, int sbase,
                                                    const float* __restrict__ Xp,
                                                    const float* __restrict__ Wih,
                                                    const float* __restrict__ bias) {
    extern __shared__ ull sm[];
    ull*   ws   = sm;              // [kpair][16 rows]              4096 ull
    ull*   red  = sm + 4096;       // recur partials, 2304 ull/chain (9216)
    ull*   red2 = sm + 13312;      // proj partials, 1280 ull/chain (5120)
    ull*   wih  = sm + 18432;      // [128 kpair][16 rows]          2048 ull
    float* ring = (float*)(sm + 20480);  // [NRING][NCH][16 r][16 b] = 6144 floats

    const int tid = threadIdx.x;
    const int bid = blockIdx.x;
    const int u0 = bid * 4;
    int w = tid >> 5, l = tid & 31;
    int q = w >> 2;                 // chain
    int wi = w & 3;                 // warp-in-chain (also SMSP)
    int b16 = l & 15, kh = l >> 4;

    // recurrent weights: [kpair][row], row = gate*4 + unit
    for (int idx = tid; idx < 4096; idx += 512) {
        int kp = idx >> 4, r = idx & 15;
        int g = r >> 2, uu = r & 3;
        ws[idx] = *(const ull*)(Whh + ((size_t)(g * HID + u0 + uu)) * HID + kp * 2);
    }
    // input-proj weights: [kpair(128)][row(16)]
    for (int idx = tid; idx < 2048; idx += 512) {
        int kp = idx >> 4, r = idx & 15;
        int g = r >> 2, uu = r & 3;
        wih[idx] = *(const ull*)(Wih + ((size_t)(g * HID + u0 + uu)) * DIN + kp * 2);
    }
    __syncthreads();

    // epilogue mapping: warps wi<2, 64 threads per chain -> (ul, eb16)
    int e = wi * 32 + l;
    int ul = (e >> 4) & 3, eb16 = e & 15;
    int u = u0 + ul;
    float c = 0.0f, bgate[4];
    if (wi < 2) {
        c = d_cbuf[u * BATCH + q * BCH + eb16];
#pragma unroll
        for (int g = 0; g < 4; g++) bgate[g] = bias[g * HID + u];
    }

    ull* rq  = red  + q * 2304;
    ull* r2q = red2 + q * 1280;
    int kbase = wi * 64 + kh * 32;
    const int barid = 1 + q;
    volatile int* epoch = &d_epoch[q * 32];
    unsigned* cg = &d_cntg[(q * 8 + (bid >> 4)) * 32];
    unsigned* cr = &d_cntr[q * 32];

    // ---- prologue: fill ring slots 0..LA-1 ----
    for (int p = 0; p < LA; p++) {
        proj_phase(wih, r2q, Xp, p, which, q, wi, kh, b16);
        barx(barid);
        if (wi < 2) {
#pragma unroll
            for (int g = 0; g < 4; g++) {
                int r = g * 4 + ul;
                const ull* pp = r2q + (size_t)(r * 16 + eb16) * 5;
                ull a0 = pp[0]; fadd2(a0, pp[1]);
                ull a1 = pp[2]; fadd2(a1, pp[3]);
                fadd2(a0, a1);
                ring[(((p % NRING) * NCH + q) * 16 + r) * 16 + eb16] = sum2(a0);
            }
        }
        barx(barid);
    }

    // ---- main loop ----
    for (int t = 0; t < TSTEPS; t++) {
        int s = sbase + t;
        int tp = t + LA;
        bool doP = (tp < TSTEPS);

        // proj for step t+LA: useful work that overlaps the epoch wait below
        if (doP) proj_phase(wih, r2q, Xp, tp, which, q, wi, kh, b16);

        // wait for h_s (single poller per chain per block)
        if (wi == 0 && l == 0) { while (ld_acq(epoch) < s) { } }
        barx(barid);

        const ull* hsrc = (const ull*)d_hq[q][s & 1] + b16;
        ull acc[16];
#pragma unroll
        for (int r = 0; r < 16; r++) acc[r] = 0ull;

        ull hg[2][8];
#pragma unroll
        for (int j = 0; j < 8; j++) hg[0][j] = ldcg64(hsrc + (size_t)(kbase + j) * BCH);
#pragma unroll
        for (int g4 = 0; g4 < 4; g4++) {
            int cur = g4 & 1, nxt = cur ^ 1;
            if (g4 < 3) {
#pragma unroll
                for (int j = 0; j < 8; j++)
                    hg[nxt][j] = ldcg64(hsrc + (size_t)(kbase + (g4 + 1) * 8 + j) * BCH);
            }
#pragma unroll
            for (int j = 0; j < 8; j++) {
                const ulonglong2* wp = (const ulonglong2*)(ws + (size_t)(kbase + g4 * 8 + j) * 16);
                ull hv = hg[cur][j];
#pragma unroll
                for (int rp = 0; rp < 8; rp++) {
                    ulonglong2 wv = wp[rp];
                    fma2(acc[2 * rp],     wv.x, hv);
                    fma2(acc[2 * rp + 1], wv.y, hv);
                }
            }
        }
#pragma unroll
        for (int r = 0; r < 16; r++)
            rq[(size_t)(r * 16 + b16) * 9 + wi * 2 + kh] = acc[r];
        barx(barid);                        // partials ready; h_s reads done

        if (wi < 2) {
            float gate[4];
#pragma unroll
            for (int g = 0; g < 4; g++) {
                int r = g * 4 + ul;
                const ull* rp_ = rq + (size_t)(r * 16 + eb16) * 9;
                ull a0 = rp_[0]; fadd2(a0, rp_[1]); fadd2(a0, rp_[2]); fadd2(a0, rp_[3]);
                ull a1 = rp_[4]; fadd2(a1, rp_[5]); fadd2(a1, rp_[6]); fadd2(a1, rp_[7]);
                fadd2(a0, a1);
                gate[g] = sum2(a0) + bgate[g]
                        + ring[(((t % NRING) * NCH + q) * 16 + r) * 16 + eb16];
            }
            float iv = fsig(gate[0]);
            float fv = fsig(gate[1]);
            float gv = ftanh(gate[2]);
            float ov = fsig(gate[3]);
            c = fv * c + iv * gv;
            float h = ov * ftanh(c);

            d_hq[q][(s + 1) & 1][((u >> 1) * BCH + eb16) * 2 + (u & 1)] = h;
            if (which) d_hs[((size_t)t * HID + u) * BATCH + q * BCH + eb16] = h;

            // reduce proj partials for t+LA into the ring
            if (doP) {
#pragma unroll
                for (int g = 0; g < 4; g++) {
                    int r = g * 4 + ul;
                    const ull* pp = r2q + (size_t)(r * 16 + eb16) * 5;
                    ull a0 = pp[0]; fadd2(a0, pp[1]);
                    ull a1 = pp[2]; fadd2(a1, pp[3]);
                    fadd2(a0, a1);
                    ring[(((tp % NRING) * NCH + q) * 16 + r) * 16 + eb16] = sum2(a0);
                }
            }
        }
        barx(barid);                        // h stores + red2 reads done chain-wide

        // tree arrival: group counter (16 blocks) -> root (8 groups) -> epoch
        if (wi == 3 && l == 0) {
            __threadfence();
            unsigned og = atomicAdd(cg, 1u);
            if (og == 16u * (unsigned)(s + 1) - 1u) {
                unsigned orr = atomicAdd(cr, 1u);
                if (orr == 8u * (unsigned)(s + 1) - 1u) st_rel(epoch, s + 1);
            }
        }
    }
    if (wi < 2) d_cbuf[u * BATCH + q * BCH + eb16] = c;   // enc -> dec handoff
}

// ---------------- softmax over last dim (256), one warp per (t,b) row ----------------
__global__ __launch_bounds__(256) void softmax_kernel(float* __restrict__ out) {
    int row = blockIdx.x * 8 + (threadIdx.x >> 5);
    if (row >= TSTEPS * BATCH) return;
    int lane = threadIdx.x & 31;
    const float* lp = d_logits + (size_t)row * DOUT;
    float v[8];
    float m = -INFINITY;
#pragma unroll
    for (int i = 0; i < 8; i++) { v[i] = lp[lane + 32 * i]; m = fmaxf(m, v[i]); }
#pragma unroll
    for (int o = 16; o > 0; o >>= 1) m = fmaxf(m, __shfl_xor_sync(0xffffffffu, m, o));
    float s = 0.0f;
#pragma unroll
    for (int i = 0; i < 8; i++) { v[i] = expf(v[i] - m); s += v[i]; }
#pragma unroll
    for (int o = 16; o > 0; o >>= 1) s += __shfl_xor_sync(0xffffffffu, s, o);
    float inv = 1.0f / s;
    float* op = out + (size_t)row * DOUT;
#pragma unroll
    for (int i = 0; i < 8; i++) op[lane + 32 * i] = v[i] * inv;
}

// ---------------- launch ----------------
extern "C" void kernel_launch(void* const* d_in, const int* in_sizes, int n_in,
                              void* d_out, int out_size) {
    const float* x      = (const float*)d_in[0];
    const float* target = (const float*)d_in[1];
    const float* h0     = (const float*)d_in[2];
    const float* c0     = (const float*)d_in[3];
    const float* eWih   = (const float*)d_in[4];
    const float* eWhh   = (const float*)d_in[5];
    const float* eb     = (const float*)d_in[6];
    const float* dWih   = (const float*)d_in[7];
    const float* dWhh   = (const float*)d_in[8];
    const float* db     = (const float*)d_in[9];
    const float* fcW    = (const float*)d_in[10];
    const float* fcb    = (const float*)d_in[11];
    float* out = (float*)d_out;

    // smem: ws 4096 + red 9216 + red2 5120 + wih 2048 + ring 3072 = 23552 ull = 188416 B
    const int smem_recur = 23552 * 8;
    cudaFuncSetAttribute(recur_kernel, cudaFuncAttributeMaxDynamicSharedMemorySize, smem_recur);

    init_state<<<128, 256>>>(h0, c0);

    float* ghs;  cudaGetSymbolAddress((void**)&ghs,  d_hs);
    float* glog; cudaGetSymbolAddress((void**)&glog, d_logits);

    // encoder recurrence with fused enc input projection
    recur_kernel<<<NBLK, 512, smem_recur>>>(eWhh, 0, 0, x, eWih, eb);
    // decoder recurrence with fused dec input projection (teacher-forced target)
    recur_kernel<<<NBLK, 512, smem_recur>>>(dWhh, 1, TSTEPS, target, dWih, db);

    gemm_kernel<<<dim3(2, TSTEPS), 256>>>(ghs, fcW, fcb, glog, DOUT, HID, HID / 32);
    softmax_kernel<<<(TSTEPS * BATCH + 7) / 8, 256>>>(out);
}

// round 17
// speedup vs baseline: 1.4939x; 1.4939x over previous
#include <cuda_runtime.h>
#include <math.h>

#define TSTEPS 512
#define BATCH  64
#define DIN    256
#define HID    512
#define DOUT   256
#define G4H    2048
#define NBLK   128
#define NCH    4      // batch chains
#define BCH    16     // batches per chain

typedef unsigned long long ull;

// ---------------- scratch ----------------
__device__ float d_Genc[(size_t)TSTEPS * G4H * BATCH];    // [t][gate*512+u][b]
__device__ float d_Gdec[(size_t)TSTEPS * G4H * BATCH];
__device__ float d_hq[NCH][2][256 * BCH * 2];             // [chain][parity][kpair][b16][2]
__device__ float d_cbuf[HID * BATCH];                     // [u][b]
__device__ float d_hs[(size_t)TSTEPS * HID * BATCH];      // [t][u][b]
__device__ float d_logits[(size_t)TSTEPS * BATCH * DOUT]; // [t][b][n]
__device__ unsigned d_cntg[NCH * 8 * 32];                 // group counters (stride-32 lines)
__device__ unsigned d_cntr[NCH * 32];                     // root counters
__device__ volatile int d_epoch[NCH * 32];                // broadcast line per chain

// ---------------- helpers ----------------
__device__ __forceinline__ void fma2(ull& a, ull x, ull y) {
    asm("fma.rn.f32x2 %0, %1, %2, %3;" : "=l"(a) : "l"(x), "l"(y), "l"(a));
}
__device__ __forceinline__ void fadd2(ull& a, ull x) {
    asm("add.rn.f32x2 %0, %1, %2;" : "=l"(a) : "l"(a), "l"(x));
}
__device__ __forceinline__ ull pack2(float lo, float hi) {
    ull r; asm("mov.b64 %0, {%1, %2};" : "=l"(r) : "f"(lo), "f"(hi)); return r;
}
__device__ __forceinline__ float sum2(ull v) {
    float lo, hi; asm("mov.b64 {%0, %1}, %2;" : "=f"(lo), "=f"(hi) : "l"(v));
    return lo + hi;
}
__device__ __forceinline__ ull ldcg64(const ull* p) {
    ull v; asm volatile("ld.global.cg.u64 %0, [%1];" : "=l"(v) : "l"(p)); return v;
}
__device__ __forceinline__ int ld_acq(const volatile int* p) {
    int v; asm volatile("ld.acquire.gpu.global.s32 %0, [%1];" : "=r"(v) : "l"(p) : "memory");
    return v;
}
__device__ __forceinline__ void st_rel(volatile int* p, int v) {
    asm volatile("st.release.gpu.global.s32 [%0], %1;" :: "l"(p), "r"(v) : "memory");
}
__device__ __forceinline__ unsigned atom_add_ar(unsigned* p, unsigned v) {
    unsigned old;
    asm volatile("atom.acq_rel.gpu.global.add.u32 %0, [%1], %2;"
                 : "=r"(old) : "l"(p), "r"(v) : "memory");
    return old;
}
__device__ __forceinline__ void barx(int id) {
    asm volatile("bar.sync %0, 128;" :: "r"(id) : "memory");
}
__device__ __forceinline__ float fsig(float x) {
    return __fdividef(1.0f, 1.0f + __expf(-x));
}
__device__ __forceinline__ float ftanh(float x) {
    float e = __expf(2.0f * x);                 // inf-safe
    return 1.0f - __fdividef(2.0f, e + 1.0f);
}

// ---------------- init: pack initial h/c per chain, reset sync state ----------------
__global__ __launch_bounds__(256) void init_state(const float* __restrict__ h0,
                                                  const float* __restrict__ c0) {
    int i = blockIdx.x * blockDim.x + threadIdx.x;
    if (i < NCH * 8) d_cntg[i * 32] = 0u;
    if (i < NCH) { d_cntr[i * 32] = 0u; d_epoch[i * 32] = 0; }
    if (i >= HID * BATCH) return;
    int b = i >> 9;                 // h0 layout [1][B][H]
    int u = i & 511;
    int q = b >> 4, b16 = b & 15;
    d_hq[q][0][((u >> 1) * BCH + b16) * 2 + (u & 1)] = h0[i];
    d_cbuf[u * BATCH + b] = c0[i];
}

// ---------------- unified register-blocked GEMM (R9-proven) ----------------
__global__ __launch_bounds__(256, 2) void gemm_kernel(
    const float* __restrict__ X, const float* __restrict__ W,
    const float* __restrict__ bias, float* __restrict__ Out,
    int Ntot, int K, int kchunks, int dec_shift, int x_kb, int out_bn) {
    __shared__ ull Wt[16 * 130];
    __shared__ ull Xt[16 * 66];

    int t  = blockIdx.y;
    int n0 = blockIdx.x * 128;
    int tid = threadIdx.x;
    int tx = tid & 15, ty = tid >> 4;

    ull acc[8][4];
#pragma unroll
    for (int i = 0; i < 8; i++)
#pragma unroll
        for (int j = 0; j < 4; j++) acc[i][j] = 0ull;

    for (int ch = 0; ch < kchunks; ch++) {
        for (int idx = tid; idx < 2048; idx += 256) {
            int kk = idx & 15, n = idx >> 4;
            Wt[kk * 130 + n] = *(const ull*)(W + (size_t)(n0 + n) * K + ch * 32 + kk * 2);
        }
        if (x_kb) {
            for (int idx = tid; idx < 1024; idx += 256) {
                int b = idx & 63, kk = idx >> 6;
                int kg = ch * 32 + kk * 2;
                Xt[kk * 66 + b] = pack2(X[((size_t)t * K + kg) * 64 + b],
                                        X[((size_t)t * K + kg + 1) * 64 + b]);
            }
        } else {
            bool zero = (dec_shift && t == 0);
            int trow = t - dec_shift;
            for (int idx = tid; idx < 1024; idx += 256) {
                int kk = idx & 15, b = idx >> 4;
                Xt[kk * 66 + b] = zero ? 0ull
                    : *(const ull*)(X + ((size_t)trow * 64 + b) * K + ch * 32 + kk * 2);
            }
        }
        __syncthreads();
#pragma unroll
        for (int kk = 0; kk < 16; kk++) {
            ulonglong2 xv0 = *(const ulonglong2*)&Xt[kk * 66 + tx * 4];
            ulonglong2 xv1 = *(const ulonglong2*)&Xt[kk * 66 + tx * 4 + 2];
            ull xs0 = xv0.x, xs1 = xv0.y, xs2 = xv1.x, xs3 = xv1.y;
#pragma unroll
            for (int q = 0; q < 4; q++) {
                ulonglong2 wv = *(const ulonglong2*)&Wt[kk * 130 + ty * 8 + 2 * q];
                fma2(acc[2 * q][0], wv.x, xs0);
                fma2(acc[2 * q][1], wv.x, xs1);
                fma2(acc[2 * q][2], wv.x, xs2);
                fma2(acc[2 * q][3], wv.x, xs3);
                fma2(acc[2 * q + 1][0], wv.y, xs0);
                fma2(acc[2 * q + 1][1], wv.y, xs1);
                fma2(acc[2 * q + 1][2], wv.y, xs2);
                fma2(acc[2 * q + 1][3], wv.y, xs3);
            }
        }
        __syncthreads();
    }

    if (out_bn) {
        float bb[8];
#pragma unroll
        for (int i = 0; i < 8; i++) bb[i] = bias[n0 + ty * 8 + i];
#pragma unroll
        for (int j = 0; j < 4; j++) {
            int b = tx * 4 + j;
            float v[8];
#pragma unroll
            for (int i = 0; i < 8; i++) v[i] = sum2(acc[i][j]) + bb[i];
            float* op = Out + ((size_t)t * 64 + b) * Ntot + n0 + ty * 8;
            *(float4*)op       = make_float4(v[0], v[1], v[2], v[3]);
            *(float4*)(op + 4) = make_float4(v[4], v[5], v[6], v[7]);
        }
    } else {
#pragma unroll
        for (int i = 0; i < 8; i++) {
            int n = n0 + ty * 8 + i;
            float bb = bias[n];
            float4 o = make_float4(sum2(acc[i][0]) + bb, sum2(acc[i][1]) + bb,
                                   sum2(acc[i][2]) + bb, sum2(acc[i][3]) + bb);
            *(float4*)(Out + ((size_t)t * Ntot + n) * 64 + tx * 4) = o;
        }
    }
}

// reduce 8 warp-partials of one gate row for batch eb
__device__ __forceinline__ float redrow(const ull* rq, int r, int eb) {
    const ull* rp = rq + (size_t)(r * 16 + eb) * 9;
    ull a0 = rp[0]; fadd2(a0, rp[1]); fadd2(a0, rp[2]); fadd2(a0, rp[3]);
    ull a1 = rp[4]; fadd2(a1, rp[5]); fadd2(a1, rp[6]); fadd2(a1, rp[7]);
    fadd2(a0, a1);
    return sum2(a0);
}

// ---------------- persistent recurrent LSTM: 4 chains, tree arrival (acq_rel) ----------------
// R14 skeleton. Epilogue now uses ALL 4 chain warps: warp wi owns unit u0+wi;
// lanes 0-15 reduce gates i,f (and own c), lanes 16-31 reduce g,o; activations
// exchanged with one shfl.bfly pair. d_hs store moved off the critical path.
__global__ __launch_bounds__(512) void recur_kernel(const float* __restrict__ Whh,
                                                    int which, int sbase,
                                                    const float* __restrict__ bias) {
    extern __shared__ ull sm[];
    ull* ws  = sm;            // [kpair][16 rows]   4096 ull = 32 KB
    ull* red = sm + 4096;     // per chain: [(row*16+b16)*9 + slot], 2304 ull each

    const float* __restrict__ G = which ? d_Gdec : d_Genc;
    int tid = threadIdx.x;
    int w = tid >> 5, l = tid & 31;
    int q = w >> 2;                 // chain
    int wi = w & 3;                 // warp-in-chain (also SMSP)
    int b16 = l & 15, kh = l >> 4;  // FMA lane mapping
    int u0 = blockIdx.x * 4;
    int bid = blockIdx.x;

    // weights: [kpair][row], row = gate*4 + unit
    for (int idx = tid; idx < 4096; idx += 512) {
        int kp = idx >> 4, r = idx & 15;
        int g = r >> 2, uu = r & 3;
        ws[idx] = *(const ull*)(Whh + ((size_t)(g * HID + u0 + uu)) * HID + kp * 2);
    }
    __syncthreads();

    // epilogue mapping: warp wi -> unit u0+wi; lane half -> gate pair
    int eb = l & 15;                // batch within chain
    bool lo = (l < 16);             // lo: gates i,f (owns c); hi: gates g,o
    int u = u0 + wi;
    int rA = (lo ? 0 : 8) + wi;     // gate row (i or g)
    int rB = (lo ? 4 : 12) + wi;    // gate row (f or o)
    float c = 0.0f, bA = 0.0f, bB = 0.0f;
    if (lo) {
        c  = d_cbuf[u * BATCH + q * BCH + eb];
        bA = bias[0 * HID + u];     // i
        bB = bias[1 * HID + u];     // f
    } else {
        bA = bias[2 * HID + u];     // g
        bB = bias[3 * HID + u];     // o
    }

    ull* rq = red + q * 2304;
    int kbase = wi * 64 + kh * 32;
    const int barid = 1 + q;
    volatile int* epoch = &d_epoch[q * 32];
    unsigned* cg = &d_cntg[(q * 8 + (bid >> 4)) * 32];
    unsigned* cr = &d_cntr[q * 32];

    for (int t = 0; t < TSTEPS; t++) {
        int s = sbase + t;

        // prefetch this thread's 2 gate inputs (LDGs overlap the wait)
        size_t gb = ((size_t)t * G4H + u) * BATCH + q * BCH + eb;
        float pA, pB;
        if (lo) { pA = G[gb];                      pB = G[gb + (size_t)512 * 64]; }
        else    { pA = G[gb + (size_t)1024 * 64];  pB = G[gb + (size_t)1536 * 64]; }

        // wait for h_s (single poller per chain per block)
        if (wi == 0 && l == 0) { while (ld_acq(epoch) < s) { } }
        barx(barid);

        const ull* hsrc = (const ull*)d_hq[q][s & 1] + b16;
        ull acc[16];
#pragma unroll
        for (int r = 0; r < 16; r++) acc[r] = 0ull;

        ull hg[2][8];
#pragma unroll
        for (int j = 0; j < 8; j++) hg[0][j] = ldcg64(hsrc + (size_t)(kbase + j) * BCH);
#pragma unroll
        for (int g4 = 0; g4 < 4; g4++) {
            int cur = g4 & 1, nxt = cur ^ 1;
            if (g4 < 3) {
#pragma unroll
                for (int j = 0; j < 8; j++)
                    hg[nxt][j] = ldcg64(hsrc + (size_t)(kbase + (g4 + 1) * 8 + j) * BCH);
            }
#pragma unroll
            for (int j = 0; j < 8; j++) {
                const ulonglong2* wp = (const ulonglong2*)(ws + (size_t)(kbase + g4 * 8 + j) * 16);
                ull hv = hg[cur][j];
#pragma unroll
                for (int rp = 0; rp < 8; rp++) {
                    ulonglong2 wv = wp[rp];
                    fma2(acc[2 * rp],     wv.x, hv);
                    fma2(acc[2 * rp + 1], wv.y, hv);
                }
            }
        }
#pragma unroll
        for (int r = 0; r < 16; r++)
            rq[(size_t)(r * 16 + b16) * 9 + wi * 2 + kh] = acc[r];
        barx(barid);                        // partials ready; h_s reads done

        // epilogue: all 4 warps; thread reduces its 2 gate rows
        float vA = redrow(rq, rA, eb) + bA + pA;
        float vB = redrow(rq, rB, eb) + bB + pB;
        float aA, aB;
        if (lo) { aA = fsig(vA);  aB = fsig(vB); }   // iv, fv
        else    { aA = ftanh(vA); aB = fsig(vB); }   // gv, ov
        float xA = __shfl_xor_sync(0xffffffffu, aA, 16);
        float xB = __shfl_xor_sync(0xffffffffu, aB, 16);
        float h = 0.0f;
        if (lo) {
            c = aB * c + aA * xA;            // f*c + i*g
            h = xB * ftanh(c);               // o * tanh(c)
            d_hq[q][(s + 1) & 1][((u >> 1) * BCH + eb) * 2 + (u & 1)] = h;
        }
        barx(barid);                        // h_{s+1} stores done chain-wide

        // tree arrival: acq_rel RMWs carry the release of the h stores
        if (wi == 3 && l == 0) {
            unsigned og = atom_add_ar(cg, 1u);
            if (og == 16u * (unsigned)(s + 1) - 1u) {
                unsigned orr = atom_add_ar(cr, 1u);
                if (orr == 8u * (unsigned)(s + 1) - 1u) st_rel(epoch, s + 1);
            }
        }
        // off critical path: hs history for the FC (consumed after kernel end)
        if (which && lo) d_hs[((size_t)t * HID + u) * BATCH + q * BCH + eb] = h;
    }
    if (lo) d_cbuf[u * BATCH + q * BCH + eb] = c;   // enc -> dec handoff
}

// ---------------- softmax over last dim (256), one warp per (t,b) row ----------------
__global__ __launch_bounds__(256) void softmax_kernel(float* __restrict__ out) {
    int row = blockIdx.x * 8 + (threadIdx.x >> 5);
    if (row >= TSTEPS * BATCH) return;
    int lane = threadIdx.x & 31;
    const float* lp = d_logits + (size_t)row * DOUT;
    float v[8];
    float m = -INFINITY;
#pragma unroll
    for (int i = 0; i < 8; i++) { v[i] = lp[lane + 32 * i]; m = fmaxf(m, v[i]); }
#pragma unroll
    for (int o = 16; o > 0; o >>= 1) m = fmaxf(m, __shfl_xor_sync(0xffffffffu, m, o));
    float s = 0.0f;
#pragma unroll
    for (int i = 0; i < 8; i++) { v[i] = expf(v[i] - m); s += v[i]; }
#pragma unroll
    for (int o = 16; o > 0; o >>= 1) s += __shfl_xor_sync(0xffffffffu, s, o);
    float inv = 1.0f / s;
    float* op = out + (size_t)row * DOUT;
#pragma unroll
    for (int i = 0; i < 8; i++) op[lane + 32 * i] = v[i] * inv;
}

// ---------------- launch ----------------
extern "C" void kernel_launch(void* const* d_in, const int* in_sizes, int n_in,
                              void* d_out, int out_size) {
    const float* x      = (const float*)d_in[0];
    const float* target = (const float*)d_in[1];
    const float* h0     = (const float*)d_in[2];
    const float* c0     = (const float*)d_in[3];
    const float* eWih   = (const float*)d_in[4];
    const float* eWhh   = (const float*)d_in[5];
    const float* eb     = (const float*)d_in[6];
    const float* dWih   = (const float*)d_in[7];
    const float* dWhh   = (const float*)d_in[8];
    const float* db     = (const float*)d_in[9];
    const float* fcW    = (const float*)d_in[10];
    const float* fcb    = (const float*)d_in[11];
    float* out = (float*)d_out;

    const int smem_recur = (4096 + NCH * 2304) * 8;   // 106496 B
    cudaFuncSetAttribute(recur_kernel, cudaFuncAttributeMaxDynamicSharedMemorySize, smem_recur);

    init_state<<<128, 256>>>(h0, c0);

    float* genc; cudaGetSymbolAddress((void**)&genc, d_Genc);
    float* gdec; cudaGetSymbolAddress((void**)&gdec, d_Gdec);
    float* ghs;  cudaGetSymbolAddress((void**)&ghs,  d_hs);
    float* glog; cudaGetSymbolAddress((void**)&glog, d_logits);

    // input projections WITHOUT bias folded (bias added in recur epilogue);
    // pass a zero-bias trick: bias ptr reused but epilogue adds it — so here
    // we must NOT double-add. Use the recur-side bias only: proj writes pure
    // x @ Wih^T. Achieved by passing the weight's own bias=nullptr-safe path:
    // gemm adds bias[n]; keep behavior identical to R14 by passing real bias
    // and NOT adding in recur. -> To stay exactly R14-equivalent, proj keeps
    // the bias and recur adds zero.
    gemm_kernel<<<dim3(16, TSTEPS), 256>>>(x,      eWih, eb, genc, G4H, DIN, DIN / 32, 0, 0, 0);
    gemm_kernel<<<dim3(16, TSTEPS), 256>>>(target, dWih, db, gdec, G4H, DOUT, DOUT / 32, 1, 0, 0);

    // recur adds bias again? NO: pass zero bias to recur via d_logits scratch?
    // Simplest correct: recur bias = all-zeros region. d_logits is overwritten
    // later; use a dedicated zero buffer: d_cntg area is too small. Use the
    // fact that proj already added bias: give recur a zero vector.
    static float* zbias = nullptr;
    if (!zbias) {
        // use the tail of d_Genc's first time-slice? It holds live data.
        // Instead: d_logits is not read before fc writes it; but recur reads
        // bias BEFORE fc runs -> contents are stale/poisoned. Need true zeros:
        // init_state zeroes the first 2048 floats of d_logits for this.
        cudaGetSymbolAddress((void**)&zbias, d_logits);
    }
    // zero the first 2048 floats of d_logits (zbias) — done via a tiny kernel
    // folded into init_state is cleaner, but a memset-like launch works:
    cudaMemsetAsync(zbias, 0, G4H * sizeof(float));

    recur_kernel<<<NBLK, 512, smem_recur>>>(eWhh, 0, 0, zbias);
    recur_kernel<<<NBLK, 512, smem_recur>>>(dWhh, 1, TSTEPS, zbias);

    gemm_kernel<<<dim3(2, TSTEPS), 256>>>(ghs, fcW, fcb, glog, DOUT, HID, HID / 32, 0, 1, 1);
    softmax_kernel<<<(TSTEPS * BATCH + 7) / 8, 256>>>(out);
}